// round 10
// baseline (speedup 1.0000x reference)
#include <cuda_runtime.h>
#include <cuda_bf16.h>
#include <cstdint>

// ---- problem dims ----------------------------------------------------------
#define BV 16                      // B*V
#define ROWS_PER_BV 65536          // T*N*D
#define Mq 128                     // rows per block
#define Nq 64                      // F_OUT
#define Kq 64                      // F_IN
#define Rq 16
#define RVq 4
#define TPB 256                    // 8 warps: 4 row-groups x 2 n-halves

#define SWZ(o) ((o) ^ (((o) >> 3) & 0x70))

__device__ __forceinline__ uint32_t smem_u32(const void* p) {
    uint32_t a;
    asm("{ .reg .u64 t; cvta.to.shared.u64 t, %1; cvt.u32.u64 %0, t; }" : "=r"(a) : "l"(p));
    return a;
}

__device__ __forceinline__ uint32_t pack_bf16x2(float lo, float hi) {
    __nv_bfloat16 l = __float2bfloat16(lo), h = __float2bfloat16(hi);
    return ((uint32_t)__bfloat16_as_ushort(h) << 16) | __bfloat16_as_ushort(l);
}

__device__ __forceinline__ void ldmatrix_x4(uint32_t& r0, uint32_t& r1,
                                            uint32_t& r2, uint32_t& r3, uint32_t addr) {
    asm volatile("ldmatrix.sync.aligned.m8n8.x4.shared.b16 {%0,%1,%2,%3}, [%4];"
                 : "=r"(r0), "=r"(r1), "=r"(r2), "=r"(r3) : "r"(addr));
}

__device__ __forceinline__ void mma_bf16(float* c, const uint32_t* a,
                                         uint32_t b0, uint32_t b1) {
    asm volatile(
        "mma.sync.aligned.m16n8k16.row.col.f32.bf16.bf16.f32 "
        "{%0,%1,%2,%3}, {%4,%5,%6,%7}, {%8,%9}, {%0,%1,%2,%3};"
        : "+f"(c[0]), "+f"(c[1]), "+f"(c[2]), "+f"(c[3])
        : "r"(a[0]), "r"(a[1]), "r"(a[2]), "r"(a[3]), "r"(b0), "r"(b1));
}

// ---- single fused kernel ----------------------------------------------------
// Each block: (1) stages its 128-row x tile as bf16 hi/lo, (2) computes its
// bv's W = fac_in^T (sum_A fv_A core_A) fac_out, split bf16 hi/lo into mma
// B-fragments in smem, (3) 3-chain error-compensated bf16 MMA, direct stores.
__global__ void __launch_bounds__(TPB, 3)
tucker_fused_kernel(const float* __restrict__ x,
                    const int* __restrict__ var_idx,
                    const float* __restrict__ core,        // (RV, R, R)
                    const float* __restrict__ factor_vars, // (NVAR, RV)
                    const float* __restrict__ fac_in,      // (R, 64)
                    const float* __restrict__ fac_out,     // (R, 64)
                    float* __restrict__ out) {
    __shared__ __align__(1024) char sAH[Mq * 128];   // 16 KB bf16 hi, SW128 rows
    __shared__ __align__(1024) char sAL[Mq * 128];   // 16 KB bf16 lo
    __shared__ __align__(16) uint4 sB[4 * 8 * 32];   // 16 KB B fragments (ceff aliased early)

    const int bv   = blockIdx.y;
    const int t    = threadIdx.x;
    const int w    = t >> 5, lane = t & 31;
    const int rw   = w & 3;          // row group: rows rw*32 .. rw*32+31
    const int nh   = w >> 2;         // n-half: nt in [nh*4, nh*4+4)
    const size_t base = ((size_t)bv * ROWS_PER_BV + (size_t)blockIdx.x * Mq) * (size_t)Kq;

    // ---- stage A: fp32 -> bf16 hi/lo, swizzled 128B rows; 8 x LDG.128/thread
    {
        const float4* gx = (const float4*)(x + base);
        #pragma unroll
        for (int it = 0; it < 8; ++it) {
            int i = it * TPB + t;                        // float4 id: row=i>>4, c4=i&15
            float4 v = gx[i];
            float h0 = __bfloat162float(__float2bfloat16(v.x));
            float h1 = __bfloat162float(__float2bfloat16(v.y));
            float h2 = __bfloat162float(__float2bfloat16(v.z));
            float h3 = __bfloat162float(__float2bfloat16(v.w));
            uint32_t hiA = pack_bf16x2(h0, h1);
            uint32_t hiB = pack_bf16x2(h2, h3);
            uint32_t loA = pack_bf16x2(v.x - h0, v.y - h1);
            uint32_t loB = pack_bf16x2(v.z - h2, v.w - h3);
            uint32_t off = SWZ((uint32_t)((i >> 4) * 128 + (i & 15) * 8));
            *(uint2*)(sAH + off) = make_uint2(hiA, hiB);
            *(uint2*)(sAL + off) = make_uint2(loA, loB);
        }
    }

    // ---- in-block W precompute -> B fragments in sB -------------------------
    {
        float* sW = (float*)sB;                          // ceff scratch (256 floats)
        const int vi = var_idx[bv];
        float fv0 = factor_vars[vi * RVq + 0];
        float fv1 = factor_vars[vi * RVq + 1];
        float fv2 = factor_vars[vi * RVq + 2];
        float fv3 = factor_vars[vi * RVq + 3];
        // ceff: one (r,c) entry per thread
        sW[t] = fv0 * core[0 * 256 + t] + fv1 * core[1 * 256 + t]
              + fv2 * core[2 * 256 + t] + fv3 * core[3 * 256 + t];
        __syncthreads();

        const int e   = t & 63;          // output column
        const int kt4 = t >> 6;          // k-tile 0..3
        // H[r] = sum_c ceff[r][c] * fac_out[c][e]   (ceff warp-uniform broadcast)
        float H[Rq];
        #pragma unroll
        for (int r = 0; r < Rq; ++r) {
            float s = 0.f;
            #pragma unroll
            for (int c = 0; c < Rq; ++c) s += sW[r * Rq + c] * fac_out[c * Nq + e];
            H[r] = s;
        }
        __syncthreads();                 // all ceff reads done before frag overwrite

        // this thread's 16 a-values: a = 16*kt4 + j   (fac_in reads warp-uniform)
        float Wh[16], Wl[16];
        #pragma unroll
        for (int j = 0; j < 16; ++j) {
            int a = 16 * kt4 + j;
            float s = 0.f;
            #pragma unroll
            for (int r = 0; r < Rq; ++r) s += fac_in[r * Kq + a] * H[r];
            float hi = __bfloat162float(__float2bfloat16(s));
            Wh[j] = hi;
            Wl[j] = s - hi;
        }
        // pack fragments: col n=e -> nt=e>>3, lanes (e&7)*4 + tig, local k0=2*tig
        int nt = e >> 3, c4 = (e & 7) * 4;
        #pragma unroll
        for (int tig = 0; tig < 4; ++tig) {
            int k0 = 2 * tig;
            sB[((kt4 * 8) + nt) * 32 + c4 + tig] =
                make_uint4(pack_bf16x2(Wh[k0],     Wh[k0 + 1]),
                           pack_bf16x2(Wh[k0 + 8], Wh[k0 + 9]),
                           pack_bf16x2(Wl[k0],     Wl[k0 + 1]),
                           pack_bf16x2(Wl[k0 + 8], Wl[k0 + 9]));
        }
    }
    __syncthreads();                     // A tiles + B fragments visible

    // ---- mainloop: 3-chain bf16 MMA ----------------------------------------
    float acc[2][4][4];
    #pragma unroll
    for (int mt = 0; mt < 2; ++mt)
        #pragma unroll
        for (int j = 0; j < 4; ++j)
            #pragma unroll
            for (int q = 0; q < 4; ++q) acc[mt][j][q] = 0.f;

    const uint32_t sbAH = smem_u32(sAH), sbAL = smem_u32(sAL);
    const int arow = rw * 32 + (lane & 15);
    const int koff = (lane >> 4) * 16;

    #pragma unroll
    for (int kt = 0; kt < 4; ++kt) {
        // B fragments for this k-tile / n-half: 4 conflict-free LDS.128
        uint4 bf[4];
        #pragma unroll
        for (int j = 0; j < 4; ++j)
            bf[j] = sB[(kt * 8 + nh * 4 + j) * 32 + lane];

        #pragma unroll
        for (int mt = 0; mt < 2; ++mt) {
            uint32_t ah[4], al[4];
            uint32_t off = SWZ((uint32_t)((arow + mt * 16) * 128 + kt * 32 + koff));
            ldmatrix_x4(ah[0], ah[1], ah[2], ah[3], sbAH + off);
            ldmatrix_x4(al[0], al[1], al[2], al[3], sbAL + off);
            #pragma unroll
            for (int j = 0; j < 4; ++j) {
                float* c = acc[mt][j];
                mma_bf16(c, ah, bf[j].x, bf[j].y);       // xh * Wh
                mma_bf16(c, ah, bf[j].z, bf[j].w);       // xh * Wl
                mma_bf16(c, al, bf[j].x, bf[j].y);       // xl * Wh
            }
        }
    }

    // ---- epilogue: rows rw*32+mt*16+(lane>>2) (+8), cols nh*32+j*8+(lane&3)*2
    {
        float* ob = out + base;
        const int cc = nh * 32 + (lane & 3) * 2;
        #pragma unroll
        for (int mt = 0; mt < 2; ++mt) {
            const int r0 = rw * 32 + mt * 16 + (lane >> 2);
            float* p0 = ob + (size_t)r0 * Nq + cc;
            float* p1 = p0 + 8 * Nq;
            #pragma unroll
            for (int j = 0; j < 4; ++j) {
                *(float2*)(p0 + j * 8) = make_float2(acc[mt][j][0], acc[mt][j][1]);
                *(float2*)(p1 + j * 8) = make_float2(acc[mt][j][2], acc[mt][j][3]);
            }
        }
    }
}

extern "C" void kernel_launch(void* const* d_in, const int* in_sizes, int n_in,
                              void* d_out, int out_size) {
    const float* x           = (const float*)d_in[0];
    const int*   var_idx     = (const int*)d_in[1];
    const float* core        = (const float*)d_in[2];
    const float* factor_vars = (const float*)d_in[3];
    const float* fac_in      = (const float*)d_in[4];
    const float* fac_out     = (const float*)d_in[5];
    float* out = (float*)d_out;

    dim3 grid(ROWS_PER_BV / Mq, BV);   // (512, 16)
    tucker_fused_kernel<<<grid, TPB>>>(x, var_idx, core, factor_vars,
                                       fac_in, fac_out, out);
}

// round 11
// speedup vs baseline: 1.6270x; 1.6270x over previous
#include <cuda_runtime.h>
#include <cuda_bf16.h>
#include <cstdint>

// ---- problem dims ----------------------------------------------------------
#define BV 16                      // B*V
#define ROWS_PER_BV 65536          // T*N*D
#define Mq 128                     // rows per block
#define Nq 64                      // F_OUT
#define Kq 64                      // F_IN
#define Rq 16
#define RVq 4
#define TPB 256                    // 8 warps: 4 row-groups x 2 n-halves

#define SWZ(o) ((o) ^ (((o) >> 3) & 0x70))

// Precomputed B fragments, mma.m16n8k16 register layout, hi/lo packed:
// [bv][kt(4)][nt(8)][lane(32)] -> uint4 {bh0, bh1, bl0, bl1}
__device__ __align__(16) uint4 g_Bf[BV * 4 * 8 * 32];

__device__ __forceinline__ uint32_t smem_u32(const void* p) {
    uint32_t a;
    asm("{ .reg .u64 t; cvta.to.shared.u64 t, %1; cvt.u32.u64 %0, t; }" : "=r"(a) : "l"(p));
    return a;
}

__device__ __forceinline__ uint32_t pack_bf16x2(float lo, float hi) {
    __nv_bfloat16 l = __float2bfloat16(lo), h = __float2bfloat16(hi);
    return ((uint32_t)__bfloat16_as_ushort(h) << 16) | __bfloat16_as_ushort(l);
}

__device__ __forceinline__ void ldmatrix_x4(uint32_t& r0, uint32_t& r1,
                                            uint32_t& r2, uint32_t& r3, uint32_t addr) {
    asm volatile("ldmatrix.sync.aligned.m8n8.x4.shared.b16 {%0,%1,%2,%3}, [%4];"
                 : "=r"(r0), "=r"(r1), "=r"(r2), "=r"(r3) : "r"(addr));
}

__device__ __forceinline__ void mma_bf16(float* c, const uint32_t* a,
                                         uint32_t b0, uint32_t b1) {
    asm volatile(
        "mma.sync.aligned.m16n8k16.row.col.f32.bf16.bf16.f32 "
        "{%0,%1,%2,%3}, {%4,%5,%6,%7}, {%8,%9}, {%0,%1,%2,%3};"
        : "+f"(c[0]), "+f"(c[1]), "+f"(c[2]), "+f"(c[3])
        : "r"(a[0]), "r"(a[1]), "r"(a[2]), "r"(a[3]), "r"(b0), "r"(b1));
}

// ---- precompute: W[bv] -> bf16 hi/lo B-fragments (smem-staged inputs) ------
__global__ void precompute_kernel(const int* __restrict__ var_idx,
                                  const float* __restrict__ core,        // (RV, R, R)
                                  const float* __restrict__ factor_vars, // (NVAR, RV)
                                  const float* __restrict__ fac_in,      // (R, 64)
                                  const float* __restrict__ fac_out) {   // (R, 64)
    int bv = blockIdx.x;
    int t  = threadIdx.x;      // 0..255
    int e  = t & 63;           // output column
    int kt = t >> 6;           // k-tile 0..3

    __shared__ float fvs[RVq];
    __shared__ float sfo[Rq * Nq];   // fac_out, 4 KB
    __shared__ float sfi[Rq * Kq];   // fac_in, 4 KB
    __shared__ float ceff[Rq * Rq];

    // coalesced staging of all small operands
    if (t < RVq) fvs[t] = factor_vars[var_idx[bv] * RVq + t];
    #pragma unroll
    for (int i = 0; i < 4; ++i) {
        sfo[i * 256 + t] = fac_out[i * 256 + t];
        sfi[i * 256 + t] = fac_in[i * 256 + t];
    }
    __syncthreads();

    if (t < Rq * Rq) {
        float s = 0.f;
        #pragma unroll
        for (int A = 0; A < RVq; ++A) s += fvs[A] * core[A * Rq * Rq + t];
        ceff[t] = s;
    }
    __syncthreads();

    float H[Rq];               // H[r] = sum_c ceff[r][c] * fac_out[c][e]
    #pragma unroll
    for (int r = 0; r < Rq; ++r) {
        float s = 0.f;
        #pragma unroll
        for (int c = 0; c < Rq; ++c) s += ceff[r * Rq + c] * sfo[c * Nq + e];
        H[r] = s;
    }
    // this thread's 16 a-values: a = 16*kt + j
    float Wh[16], Wl[16];
    #pragma unroll
    for (int j = 0; j < 16; ++j) {
        int a = 16 * kt + j;
        float s = 0.f;
        #pragma unroll
        for (int r = 0; r < Rq; ++r) s += sfi[r * Kq + a] * H[r];
        float hi = __bfloat162float(__float2bfloat16(s));
        Wh[j] = hi;
        Wl[j] = s - hi;
    }
    // pack fragments: col n=e -> nt=e>>3, lanes (e&7)*4 + tig, local k0 = 2*tig
    int nt = e >> 3, c4 = (e & 7) * 4;
    #pragma unroll
    for (int tig = 0; tig < 4; ++tig) {
        int k0 = 2 * tig;
        int idx = ((bv * 4 + kt) * 8 + nt) * 32 + c4 + tig;
        g_Bf[idx] = make_uint4(pack_bf16x2(Wh[k0],     Wh[k0 + 1]),
                               pack_bf16x2(Wh[k0 + 8], Wh[k0 + 9]),
                               pack_bf16x2(Wl[k0],     Wl[k0 + 1]),
                               pack_bf16x2(Wl[k0 + 8], Wl[k0 + 9]));
    }
}

// ---- main kernel: 8 warps = 4 row-groups (32 rows) x 2 n-halves ------------
__global__ void __launch_bounds__(TPB, 3)
tucker_mma_kernel(const float* __restrict__ x, float* __restrict__ out) {
    __shared__ __align__(1024) char sAH[Mq * 128];   // 16 KB bf16 hi, SW128 rows
    __shared__ __align__(1024) char sAL[Mq * 128];   // 16 KB bf16 lo

    const int bv   = blockIdx.y;
    const int t    = threadIdx.x;
    const int w    = t >> 5, lane = t & 31;
    const int rw   = w & 3;          // row group: rows rw*32 .. rw*32+31
    const int nh   = w >> 2;         // n-half: nt in [nh*4, nh*4+4)
    const size_t base = ((size_t)bv * ROWS_PER_BV + (size_t)blockIdx.x * Mq) * (size_t)Kq;

    // ---- stage A: front-batched 8 x LDG.128, then hi/lo split -> 8 x STS.128
    {
        const float4* gx = (const float4*)(x + base);
        float4 v[8];
        #pragma unroll
        for (int p = 0; p < 4; ++p) {
            int i2 = p * TPB + t;                    // pair id: float4s 2*i2, 2*i2+1
            v[2 * p]     = gx[2 * i2];
            v[2 * p + 1] = gx[2 * i2 + 1];
        }
        #pragma unroll
        for (int p = 0; p < 4; ++p) {
            int i2 = p * TPB + t;                    // row = i2>>3, 16B chunk = i2&7
            float4 v0 = v[2 * p], v1 = v[2 * p + 1];
            float h0 = __bfloat162float(__float2bfloat16(v0.x));
            float h1 = __bfloat162float(__float2bfloat16(v0.y));
            float h2 = __bfloat162float(__float2bfloat16(v0.z));
            float h3 = __bfloat162float(__float2bfloat16(v0.w));
            float h4 = __bfloat162float(__float2bfloat16(v1.x));
            float h5 = __bfloat162float(__float2bfloat16(v1.y));
            float h6 = __bfloat162float(__float2bfloat16(v1.z));
            float h7 = __bfloat162float(__float2bfloat16(v1.w));
            uint4 hi = make_uint4(pack_bf16x2(h0, h1), pack_bf16x2(h2, h3),
                                  pack_bf16x2(h4, h5), pack_bf16x2(h6, h7));
            uint4 lo = make_uint4(pack_bf16x2(v0.x - h0, v0.y - h1),
                                  pack_bf16x2(v0.z - h2, v0.w - h3),
                                  pack_bf16x2(v1.x - h4, v1.y - h5),
                                  pack_bf16x2(v1.z - h6, v1.w - h7));
            uint32_t off = SWZ((uint32_t)((i2 >> 3) * 128 + (i2 & 7) * 16));
            *(uint4*)(sAH + off) = hi;
            *(uint4*)(sAL + off) = lo;
        }
    }
    __syncthreads();

    // accumulators: 2 m-tiles x 4 n-tiles x 4 floats = 32 regs
    float acc[2][4][4];
    #pragma unroll
    for (int mt = 0; mt < 2; ++mt)
        #pragma unroll
        for (int j = 0; j < 4; ++j)
            #pragma unroll
            for (int q = 0; q < 4; ++q) acc[mt][j][q] = 0.f;

    const uint32_t sbAH = smem_u32(sAH), sbAL = smem_u32(sAL);
    const int arow = rw * 32 + (lane & 15);
    const int koff = (lane >> 4) * 16;
    const uint4* gb = g_Bf + (bv * 4 * 8 + nh * 4) * 32 + lane;   // [kt][j] stride

    #pragma unroll
    for (int kt = 0; kt < 4; ++kt) {
        // B fragments for this k-tile / n-half: 4 direct LDG.128 (L1/L2-hot)
        uint4 bf[4];
        #pragma unroll
        for (int j = 0; j < 4; ++j)
            bf[j] = gb[(kt * 8 + j) * 32];

        #pragma unroll
        for (int mt = 0; mt < 2; ++mt) {
            uint32_t ah[4], al[4];
            uint32_t off = SWZ((uint32_t)((arow + mt * 16) * 128 + kt * 32 + koff));
            ldmatrix_x4(ah[0], ah[1], ah[2], ah[3], sbAH + off);
            ldmatrix_x4(al[0], al[1], al[2], al[3], sbAL + off);
            #pragma unroll
            for (int j = 0; j < 4; ++j) {
                float* c = acc[mt][j];
                mma_bf16(c, ah, bf[j].x, bf[j].y);       // xh * Wh
                mma_bf16(c, ah, bf[j].z, bf[j].w);       // xh * Wl
                mma_bf16(c, al, bf[j].x, bf[j].y);       // xl * Wh
            }
        }
    }

    // epilogue: rows rw*32 + mt*16 + (lane>>2) (+8), cols nh*32 + j*8 + (lane&3)*2
    {
        float* ob = out + base;
        const int cc = nh * 32 + (lane & 3) * 2;
        #pragma unroll
        for (int mt = 0; mt < 2; ++mt) {
            const int r0 = rw * 32 + mt * 16 + (lane >> 2);
            float* p0 = ob + (size_t)r0 * Nq + cc;
            float* p1 = p0 + 8 * Nq;
            #pragma unroll
            for (int j = 0; j < 4; ++j) {
                *(float2*)(p0 + j * 8) = make_float2(acc[mt][j][0], acc[mt][j][1]);
                *(float2*)(p1 + j * 8) = make_float2(acc[mt][j][2], acc[mt][j][3]);
            }
        }
    }
}

extern "C" void kernel_launch(void* const* d_in, const int* in_sizes, int n_in,
                              void* d_out, int out_size) {
    const float* x           = (const float*)d_in[0];
    const int*   var_idx     = (const int*)d_in[1];
    const float* core        = (const float*)d_in[2];
    const float* factor_vars = (const float*)d_in[3];
    const float* fac_in      = (const float*)d_in[4];
    const float* fac_out     = (const float*)d_in[5];
    float* out = (float*)d_out;

    precompute_kernel<<<BV, 256>>>(var_idx, core, factor_vars, fac_in, fac_out);

    dim3 grid(ROWS_PER_BV / Mq, BV);   // (512, 16)
    tucker_mma_kernel<<<grid, TPB>>>(x, out);
}